// round 10
// baseline (speedup 1.0000x reference)
#include <cuda_runtime.h>
#include <cuda_bf16.h>
#include <cstdint>

#define BB   16
#define NPTS 4096
#define MPTS 1024
#define C1V  256
#define C2V  256
#define CIN  512
#define H1V  256
#define H2V  256

// ---------------------------------------------------------------------------
// Device-global scratch (allocation-free per harness rules)
// ---------------------------------------------------------------------------
__device__ __nv_bfloat16 g_F1h [(size_t)BB * NPTS * C1V];   // feat1 split [b][n][c]
__device__ __nv_bfloat16 g_F1l [(size_t)BB * NPTS * C1V];
__device__ __nv_bfloat16 g_TF2h[(size_t)BB * MPTS * C2V];   // feat2^T split [b][m][c]
__device__ __nv_bfloat16 g_TF2l[(size_t)BB * MPTS * C2V];
__device__ float         g_Y   [(size_t)BB * MPTS * H1V];   // W1a*feat2  [b][m][o] fp32
__device__ __nv_bfloat16 g_X1h [(size_t)BB * NPTS * H1V];   // layer1 out split [b][n][o]
__device__ __nv_bfloat16 g_X1l [(size_t)BB * NPTS * H1V];
__device__ __nv_bfloat16 g_W1ah[H1V * C2V], g_W1al[H1V * C2V];
__device__ __nv_bfloat16 g_W1bh[H1V * C1V], g_W1bl[H1V * C1V];
__device__ __nv_bfloat16 g_W2h [H2V * H1V], g_W2l [H2V * H1V];
__device__ int   g_idx[(size_t)BB * NPTS * 3];
__device__ float g_w  [(size_t)BB * NPTS * 3];

#define FLT_BIG 3.402823466e38f

// ---------------------------------------------------------------------------
// PTX helpers (sm_80-era features only — build targets plain sm_100)
// ---------------------------------------------------------------------------
__device__ __forceinline__ uint32_t smem_u32(const void* p) {
    uint32_t a;
    asm("{ .reg .u64 t; cvta.to.shared.u64 t, %1; cvt.u32.u64 %0, t; }" : "=r"(a) : "l"(p));
    return a;
}
__device__ __forceinline__ void cpa16(uint32_t dst, const void* src) {
    asm volatile("cp.async.cg.shared.global [%0], [%1], 16;" :: "r"(dst), "l"(src));
}
__device__ __forceinline__ void ldmx4(uint32_t* r, uint32_t addr) {
    asm volatile("ldmatrix.sync.aligned.m8n8.x4.shared.b16 {%0,%1,%2,%3}, [%4];"
                 : "=r"(r[0]), "=r"(r[1]), "=r"(r[2]), "=r"(r[3]) : "r"(addr));
}
__device__ __forceinline__ void mma16816(float* d, const uint32_t* a,
                                         uint32_t b0, uint32_t b1) {
    asm volatile(
        "mma.sync.aligned.m16n8k16.row.col.f32.bf16.bf16.f32 "
        "{%0,%1,%2,%3}, {%4,%5,%6,%7}, {%8,%9}, {%0,%1,%2,%3};"
        : "+f"(d[0]), "+f"(d[1]), "+f"(d[2]), "+f"(d[3])
        : "r"(a[0]), "r"(a[1]), "r"(a[2]), "r"(a[3]), "r"(b0), "r"(b1));
}
__device__ __forceinline__ void split2(float y, __nv_bfloat16& h, __nv_bfloat16& l) {
    h = __float2bfloat16_rn(y);
    l = __float2bfloat16_rn(y - __bfloat162float(h));
}

// ---------------------------------------------------------------------------
// Fused heterogeneous prep kernel. Parts:
//   [0, 16384): even -> nn (8192), odd -> feat1 split (8192)
//   [16384, 20480): feat2 transpose + split (4096)
//   [20480, 21248): weight split: w1 de-interleaved into W1a/W1b, w2 (768)
// ---------------------------------------------------------------------------
#define NN_BLKS   (BB * NPTS / 8)                         // 8192
#define F1_BLKS   ((NPTS / 32) * (C1V / 64) * BB)         // 8192
#define F2T_BLKS  ((MPTS / 32) * (C2V / 32) * BB)         // 4096
#define WS1_BLKS  (H1V * CIN / 256)                       // 512
#define WS2_BLKS  (H2V * H1V / 256)                       // 256
#define PREP_BLKS (NN_BLKS + F1_BLKS + F2T_BLKS + WS1_BLKS + WS2_BLKS)

__global__ __launch_bounds__(256) void prep_kernel(
    const float* __restrict__ xyz1, const float* __restrict__ xyz2,
    const float* __restrict__ feat1, const float* __restrict__ feat2,
    const float* __restrict__ w1, const float* __restrict__ w2)
{
    __shared__ __align__(16) char sbuf[16384];
    const int bid = blockIdx.x;
    const int tid = threadIdx.x;

    if (bid < NN_BLKS + F1_BLKS) {
        if ((bid & 1) == 0) {
            // ---------------- nn part ----------------
            float* sx = reinterpret_cast<float*>(sbuf);
            float* sy = sx + MPTS;
            float* sz = sy + MPTS;
            float* sn = sz + MPTS;
            const int warp = tid >> 5;
            const int lane = tid & 31;
            const int p0   = (bid >> 1) * 8;
            const int b    = p0 / NPTS;

            const float* x2 = xyz2 + (size_t)b * MPTS * 3;
            for (int i = tid; i < MPTS; i += 256) {
                float a = x2[i*3+0], c = x2[i*3+1], d = x2[i*3+2];
                sx[i] = a; sy[i] = c; sz[i] = d;
                sn[i] = a*a + c*c + d*d;
            }
            __syncthreads();

            const int n = (p0 + warp) % NPTS;
            const float* q = xyz1 + ((size_t)b * NPTS + n) * 3;
            const float qx = q[0], qy = q[1], qz = q[2];
            const float qn = qx*qx + qy*qy + qz*qz;

            float d0 = FLT_BIG, d1 = FLT_BIG, d2 = FLT_BIG;
            int   i0 = -1, i1 = -1, i2 = -1;

            #pragma unroll 4
            for (int j = 0; j < MPTS / 32; j++) {
                const int m = j * 32 + lane;
                const float dot = qx*sx[m] + qy*sy[m] + qz*sz[m];
                const float d = qn + sn[m] - 2.0f * dot;
                if (d < d2) {
                    if (d < d1) {
                        d2 = d1; i2 = i1;
                        if (d < d0) { d1 = d0; i1 = i0; d0 = d; i0 = m; }
                        else        { d1 = d;  i1 = m; }
                    } else { d2 = d; i2 = m; }
                }
            }

            float rd[3]; int ri[3];
            #pragma unroll
            for (int k = 0; k < 3; k++) {
                float v = d0;
                #pragma unroll
                for (int off = 16; off; off >>= 1)
                    v = fminf(v, __shfl_xor_sync(0xffffffffu, v, off));
                const unsigned mask = __ballot_sync(0xffffffffu, d0 == v);
                const int src = __ffs(mask) - 1;
                const int widx = __shfl_sync(0xffffffffu, i0, src);
                rd[k] = v; ri[k] = widx;
                if (lane == src) { d0 = d1; i0 = i1; d1 = d2; i1 = i2; d2 = FLT_BIG; i2 = -1; }
            }

            if (lane == 0) {
                const float w0 = 1.0f / (rd[0] + 1e-8f);
                const float w1v = 1.0f / (rd[1] + 1e-8f);
                const float w2v = 1.0f / (rd[2] + 1e-8f);
                const float s  = 1.0f / (w0 + w1v + w2v);
                const size_t base = ((size_t)b * NPTS + n) * 3;
                g_w[base+0] = w0 * s; g_w[base+1] = w1v * s; g_w[base+2] = w2v * s;
                g_idx[base+0] = ri[0]; g_idx[base+1] = ri[1]; g_idx[base+2] = ri[2];
            }
        } else {
            // ---------------- feat1 -> F1 split part ----------------
            float (*s)[65] = reinterpret_cast<float(*)[65]>(sbuf);
            const int f  = bid >> 1;
            const int n0 = (f & 127) * 32;
            const int c0 = ((f >> 7) & 3) * 64;
            const int b  = f >> 9;
            for (int i = tid; i < 64 * 32; i += 256) {
                const int cl = i >> 5, nl = i & 31;
                s[nl][cl] = feat1[((size_t)b * C1V + c0 + cl) * NPTS + n0 + nl];
            }
            __syncthreads();
            const int n_l = tid >> 3, seg = tid & 7;
            const size_t orow = ((size_t)(b * NPTS + n0 + n_l)) * C1V + c0 + seg * 8;
            __nv_bfloat16 h[8], l[8];
            #pragma unroll
            for (int t = 0; t < 8; t++) split2(s[n_l][seg * 8 + t], h[t], l[t]);
            *reinterpret_cast<uint4*>(g_F1h + orow) = *reinterpret_cast<uint4*>(h);
            *reinterpret_cast<uint4*>(g_F1l + orow) = *reinterpret_cast<uint4*>(l);
        }
    } else if (bid < NN_BLKS + F1_BLKS + F2T_BLKS) {
        // ---------------- feat2 transpose + split part ----------------
        float (*s)[33] = reinterpret_cast<float(*)[33]>(sbuf);
        const int t  = bid - (NN_BLKS + F1_BLKS);
        const int m0 = (t & 31) * 32;
        const int c0 = ((t >> 5) & 7) * 32;
        const int b  = t >> 8;
        for (int i = tid; i < 1024; i += 256) {
            const int cl = i >> 5, ml = i & 31;
            s[ml][cl] = feat2[((size_t)b * C2V + c0 + cl) * MPTS + m0 + ml];
        }
        __syncthreads();
        const int ml = tid >> 3, c4 = (tid & 7) * 4;
        __nv_bfloat16 h[4], l[4];
        #pragma unroll
        for (int q = 0; q < 4; q++) split2(s[ml][c4 + q], h[q], l[q]);
        const size_t dst = ((size_t)(b * MPTS + m0 + ml)) * C2V + c0 + c4;
        *reinterpret_cast<uint2*>(g_TF2h + dst) = *reinterpret_cast<uint2*>(h);
        *reinterpret_cast<uint2*>(g_TF2l + dst) = *reinterpret_cast<uint2*>(l);
    } else {
        // ---------------- weight split part ----------------
        const int u = bid - (NN_BLKS + F1_BLKS + F2T_BLKS);
        if (u < WS1_BLKS) {
            const int i = u * 256 + tid;            // over H1V*CIN
            const int o = i >> 9, c = i & 511;
            __nv_bfloat16 h, l;
            split2(w1[i], h, l);
            if (c < 256) { g_W1ah[o * 256 + c] = h; g_W1al[o * 256 + c] = l; }
            else         { g_W1bh[o * 256 + c - 256] = h; g_W1bl[o * 256 + c - 256] = l; }
        } else {
            const int i = (u - WS1_BLKS) * 256 + tid;
            split2(w2[i], g_W2h[i], g_W2l[i]);
        }
    }
}

// ---------------------------------------------------------------------------
// bf16-split GEMM via mma.sync + epilogue modes.
//   D[o-tile 128][n-tile 128] = sum_k A[o][k] * B[b][n][k]  (3 split terms)
// MODE 0: BN+ReLU, fp32 out [b][H2V][NPTS]           (layer 2)
// MODE 2: raw fp32 transposed out [b][NTOT][256]     (Y = W1a*feat2)
// MODE 3: +gather(Y,idx,w) combine, BN+ReLU, bf16-split out [b][n][256] (layer1)
// ---------------------------------------------------------------------------
#define SMEM_GEMM 65536

template<int KTOT, int NTOT, int MODE>
__global__ __launch_bounds__(256, 2)
void gemm_mma(const __nv_bfloat16* __restrict__ Ah, const __nv_bfloat16* __restrict__ Al,
              const __nv_bfloat16* __restrict__ Bh, const __nv_bfloat16* __restrict__ Bl,
              const float* __restrict__ gamma, const float* __restrict__ beta,
              float* __restrict__ outF, __nv_bfloat16* __restrict__ outH,
              __nv_bfloat16* __restrict__ outL,
              const float* __restrict__ Yg, const int* __restrict__ idxg,
              const float* __restrict__ wg)
{
    extern __shared__ __align__(128) char smem[];
    const uint32_t sb = smem_u32(smem);
    const int tid  = threadIdx.x;
    const int wid  = tid >> 5;
    const int ln   = tid & 31;
    const int wrow = wid >> 2;
    const int wcol = wid & 3;
    const int n0   = blockIdx.x * 128;
    const int o0   = blockIdx.y * 128;
    const int b    = blockIdx.z;

    float acc[4][4][4];
    #pragma unroll
    for (int mi = 0; mi < 4; mi++)
        #pragma unroll
        for (int ni = 0; ni < 4; ni++)
            #pragma unroll
            for (int e = 0; e < 4; e++) acc[mi][ni][e] = 0.0f;

    constexpr int NC = KTOT / 32;

    const int rA  = wrow * 64 + (ln & 15);
    const int rB  = wcol * 32 + (ln & 15);
    const uint32_t sunit = (uint32_t)(ln >> 4);
    const uint32_t lswz  = (uint32_t)(ln & 7);

    auto load_chunk = [&](int c) {
        const uint32_t ab = sb + (uint32_t)(c & 1) * 32768u;
        const int k0 = c * 32;
        #pragma unroll
        for (int it = 0; it < 8; it++) {
            const int i = tid + it * 256;
            const int region = i >> 10;
            const int row = (i >> 3) & 127;
            const int s = i & 7;
            const uint32_t sw = (uint32_t)region * 16384u + (uint32_t)row * 128u
                              + (uint32_t)((s ^ (row & 7)) << 4);
            const int kofs = k0 + (s & 3) * 8;
            const void* src;
            if (region == 0)
                src = (s < 4 ? (const void*)(Ah + (size_t)(o0 + row) * KTOT + kofs)
                             : (const void*)(Al + (size_t)(o0 + row) * KTOT + kofs));
            else
                src = (s < 4 ? (const void*)(Bh + ((size_t)b * NTOT + n0 + row) * KTOT + kofs)
                             : (const void*)(Bl + ((size_t)b * NTOT + n0 + row) * KTOT + kofs));
            cpa16(ab + sw, src);
        }
        asm volatile("cp.async.commit_group;");
    };

    load_chunk(0);

    for (int c = 0; c < NC; c++) {
        if (c + 1 < NC) {
            load_chunk(c + 1);
            asm volatile("cp.async.wait_group 1;" ::: "memory");
        } else {
            asm volatile("cp.async.wait_group 0;" ::: "memory");
        }
        __syncthreads();

        const uint32_t ab = sb + (uint32_t)(c & 1) * 32768u;
        #pragma unroll
        for (int ks = 0; ks < 2; ks++) {
            const uint32_t scol = (uint32_t)(ks * 2) + sunit;
            const uint32_t kswzH = ((scol ^ lswz) << 4);
            const uint32_t kswzL = (((scol + 4u) ^ lswz) << 4);

            uint32_t bh[2][4], bl[2][4];
            #pragma unroll
            for (int np = 0; np < 2; np++) {
                const uint32_t rbase = 16384u + (uint32_t)(rB + np * 16) * 128u;
                ldmx4(bh[np], ab + rbase + kswzH);
                ldmx4(bl[np], ab + rbase + kswzL);
            }
            #pragma unroll
            for (int mi = 0; mi < 4; mi++) {
                const uint32_t abase = (uint32_t)(rA + mi * 16) * 128u;
                uint32_t ah[4], al[4];
                ldmx4(ah, ab + abase + kswzH);
                ldmx4(al, ab + abase + kswzL);
                #pragma unroll
                for (int ni = 0; ni < 4; ni++) {
                    const int np = ni >> 1, hf = ni & 1;
                    const uint32_t b0h = bh[np][hf], b1h = bh[np][2 + hf];
                    const uint32_t b0l = bl[np][hf], b1l = bl[np][2 + hf];
                    mma16816(acc[mi][ni], ah, b0h, b1h);
                    mma16816(acc[mi][ni], ah, b0l, b1l);
                    mma16816(acc[mi][ni], al, b0h, b1h);
                }
            }
        }
        __syncthreads();
    }

    // ---------------- epilogue ----------------
    const float inv = rsqrtf(1.0f + 1e-5f);
    const int g = ln >> 2, t = ln & 3;

    if (MODE == 0) {
        #pragma unroll
        for (int mi = 0; mi < 4; mi++) {
            const int o_a = o0 + wrow * 64 + mi * 16 + g;
            const int o_b = o_a + 8;
            const float scA = gamma[o_a] * inv, biA = beta[o_a];
            const float scB = gamma[o_b] * inv, biB = beta[o_b];
            float* rowA = outF + ((size_t)(b * H2V + o_a)) * NPTS + n0;
            float* rowB = outF + ((size_t)(b * H2V + o_b)) * NPTS + n0;
            #pragma unroll
            for (int ni = 0; ni < 4; ni++) {
                const int n = wcol * 32 + ni * 8 + 2 * t;
                float2 va, vb;
                va.x = fmaxf(fmaf(acc[mi][ni][0], scA, biA), 0.0f);
                va.y = fmaxf(fmaf(acc[mi][ni][1], scA, biA), 0.0f);
                vb.x = fmaxf(fmaf(acc[mi][ni][2], scB, biB), 0.0f);
                vb.y = fmaxf(fmaf(acc[mi][ni][3], scB, biB), 0.0f);
                *reinterpret_cast<float2*>(rowA + n) = va;
                *reinterpret_cast<float2*>(rowB + n) = vb;
            }
        }
    } else {
        // transpose through smem in two 64-o half-tiles; raw acc staged
        float* S = reinterpret_cast<float*>(smem);
        #pragma unroll
        for (int half = 0; half < 2; half++) {
            __syncthreads();
            if (wrow == half) {
                #pragma unroll
                for (int mi = 0; mi < 4; mi++) {
                    const int ol_a = mi * 16 + g;
                    const int ol_b = ol_a + 8;
                    #pragma unroll
                    for (int ni = 0; ni < 4; ni++) {
                        const int nl = wcol * 32 + ni * 8 + 2 * t;
                        S[ol_a * 129 + nl]     = acc[mi][ni][0];
                        S[ol_a * 129 + nl + 1] = acc[mi][ni][1];
                        S[ol_b * 129 + nl]     = acc[mi][ni][2];
                        S[ol_b * 129 + nl + 1] = acc[mi][ni][3];
                    }
                }
            }
            __syncthreads();
            const int n_l = tid >> 1, oh = (tid & 1) * 32;
            const int obase = o0 + half * 64 + oh;

            if (MODE == 2) {
                const size_t drow = ((size_t)(b * NTOT + n0 + n_l)) * H1V + obase;
                #pragma unroll
                for (int gs = 0; gs < 4; gs++) {
                    float v[8];
                    #pragma unroll
                    for (int t2 = 0; t2 < 8; t2++)
                        v[t2] = S[(oh + gs * 8 + t2) * 129 + n_l];
                    *reinterpret_cast<float4*>(outF + drow + gs * 8)     = *reinterpret_cast<float4*>(v);
                    *reinterpret_cast<float4*>(outF + drow + gs * 8 + 4) = *reinterpret_cast<float4*>(v + 4);
                }
            } else { // MODE == 3
                const size_t p3 = ((size_t)b * NPTS + n0 + n_l) * 3;
                const int j0 = idxg[p3], j1 = idxg[p3+1], j2 = idxg[p3+2];
                const float w0 = wg[p3], w1v = wg[p3+1], w2v = wg[p3+2];
                const float* Y0 = Yg + ((size_t)(b * MPTS + j0)) * H1V + obase;
                const float* Y1 = Yg + ((size_t)(b * MPTS + j1)) * H1V + obase;
                const float* Y2 = Yg + ((size_t)(b * MPTS + j2)) * H1V + obase;
                const size_t drow = ((size_t)(b * NPTS + n0 + n_l)) * H1V + obase;
                #pragma unroll
                for (int gs = 0; gs < 4; gs++) {
                    __nv_bfloat16 h[8], l[8];
                    #pragma unroll
                    for (int t2 = 0; t2 < 8; t2++) {
                        const int og = obase + gs * 8 + t2;
                        float z = S[(oh + gs * 8 + t2) * 129 + n_l]
                                + w0 * Y0[gs * 8 + t2] + w1v * Y1[gs * 8 + t2]
                                + w2v * Y2[gs * 8 + t2];
                        const float y = fmaxf(fmaf(z, gamma[og] * inv, beta[og]), 0.0f);
                        split2(y, h[t2], l[t2]);
                    }
                    *reinterpret_cast<uint4*>(outH + drow + gs * 8) = *reinterpret_cast<uint4*>(h);
                    *reinterpret_cast<uint4*>(outL + drow + gs * 8) = *reinterpret_cast<uint4*>(l);
                }
            }
        }
    }
}

// ---------------------------------------------------------------------------
extern "C" void kernel_launch(void* const* d_in, const int* in_sizes, int n_in,
                              void* d_out, int out_size)
{
    const float* xyz1   = (const float*)d_in[0];
    const float* xyz2   = (const float*)d_in[1];
    const float* feat1  = (const float*)d_in[2];
    const float* feat2  = (const float*)d_in[3];
    const float* w1     = (const float*)d_in[4];
    const float* gamma1 = (const float*)d_in[5];
    const float* beta1  = (const float*)d_in[6];
    const float* w2     = (const float*)d_in[7];
    const float* gamma2 = (const float*)d_in[8];
    const float* beta2  = (const float*)d_in[9];
    float* out = (float*)d_out;

    __nv_bfloat16 *F1h, *F1l, *TF2h, *TF2l, *X1h, *X1l;
    __nv_bfloat16 *W1ah, *W1al, *W1bh, *W1bl, *W2h, *W2l;
    float *Yg, *wg; int *idxg;
    cudaGetSymbolAddress((void**)&F1h,  g_F1h);
    cudaGetSymbolAddress((void**)&F1l,  g_F1l);
    cudaGetSymbolAddress((void**)&TF2h, g_TF2h);
    cudaGetSymbolAddress((void**)&TF2l, g_TF2l);
    cudaGetSymbolAddress((void**)&X1h,  g_X1h);
    cudaGetSymbolAddress((void**)&X1l,  g_X1l);
    cudaGetSymbolAddress((void**)&W1ah, g_W1ah);
    cudaGetSymbolAddress((void**)&W1al, g_W1al);
    cudaGetSymbolAddress((void**)&W1bh, g_W1bh);
    cudaGetSymbolAddress((void**)&W1bl, g_W1bl);
    cudaGetSymbolAddress((void**)&W2h,  g_W2h);
    cudaGetSymbolAddress((void**)&W2l,  g_W2l);
    cudaGetSymbolAddress((void**)&Yg,   g_Y);
    cudaGetSymbolAddress((void**)&idxg, g_idx);
    cudaGetSymbolAddress((void**)&wg,   g_w);

    cudaFuncSetAttribute(gemm_mma<C2V, MPTS, 2>, cudaFuncAttributeMaxDynamicSharedMemorySize, SMEM_GEMM);
    cudaFuncSetAttribute(gemm_mma<C1V, NPTS, 3>, cudaFuncAttributeMaxDynamicSharedMemorySize, SMEM_GEMM);
    cudaFuncSetAttribute(gemm_mma<H1V, NPTS, 0>, cudaFuncAttributeMaxDynamicSharedMemorySize, SMEM_GEMM);

    // 1) fused heterogeneous prep
    prep_kernel<<<PREP_BLKS, 256>>>(xyz1, xyz2, feat1, feat2, w1, w2);

    // 2) Y = W1a * feat2  -> [b][m][o] fp32 (raw, no BN)
    gemm_mma<C2V, MPTS, 2><<<dim3(MPTS / 128, H1V / 128, BB), 256, SMEM_GEMM>>>(
        W1ah, W1al, TF2h, TF2l, nullptr, nullptr, Yg, nullptr, nullptr,
        nullptr, nullptr, nullptr);

    // 3) layer 1 = W1b*feat1 + gather(Y; idx,w), BN+ReLU, split -> X1
    gemm_mma<C1V, NPTS, 3><<<dim3(NPTS / 128, H1V / 128, BB), 256, SMEM_GEMM>>>(
        W1bh, W1bl, F1h, F1l, gamma1, beta1, nullptr, X1h, X1l,
        Yg, idxg, wg);

    // 4) layer 2: W2 * X1 -> out fp32 [b][256][n], BN+ReLU
    gemm_mma<H1V, NPTS, 0><<<dim3(NPTS / 128, H2V / 128, BB), 256, SMEM_GEMM>>>(
        W2h, W2l, X1h, X1l, gamma2, beta2, out, nullptr, nullptr,
        nullptr, nullptr, nullptr);
}

// round 11
// speedup vs baseline: 1.3893x; 1.3893x over previous
#include <cuda_runtime.h>
#include <cuda_bf16.h>
#include <cstdint>

#define BB   16
#define NPTS 4096
#define MPTS 1024
#define C1V  256
#define C2V  256
#define CIN  512
#define H1V  256
#define H2V  256

// ---------------------------------------------------------------------------
// Device-global scratch (allocation-free per harness rules)
// ---------------------------------------------------------------------------
__device__ __nv_bfloat16 g_F1h [(size_t)BB * NPTS * C1V];   // feat1 split [b][n][c]
__device__ __nv_bfloat16 g_F1l [(size_t)BB * NPTS * C1V];
__device__ __nv_bfloat16 g_TF2h[(size_t)BB * MPTS * C2V];   // feat2^T split [b][m][c]
__device__ __nv_bfloat16 g_TF2l[(size_t)BB * MPTS * C2V];
__device__ float         g_Y   [(size_t)BB * MPTS * H1V];   // W1a*feat2  [b][m][o] fp32
__device__ float         g_G   [(size_t)BB * NPTS * H1V];   // gathered W1a*interp [b][n][o]
__device__ __nv_bfloat16 g_X1h [(size_t)BB * NPTS * H1V];   // layer1 out split [b][n][o]
__device__ __nv_bfloat16 g_X1l [(size_t)BB * NPTS * H1V];
__device__ __nv_bfloat16 g_W1ah[H1V * C2V], g_W1al[H1V * C2V];
__device__ __nv_bfloat16 g_W1bh[H1V * C1V], g_W1bl[H1V * C1V];
__device__ __nv_bfloat16 g_W2h [H2V * H1V], g_W2l [H2V * H1V];
__device__ int   g_idx[(size_t)BB * NPTS * 3];
__device__ float g_w  [(size_t)BB * NPTS * 3];

#define FLT_BIG 3.402823466e38f

// ---------------------------------------------------------------------------
// PTX helpers (sm_80-era features only — build targets plain sm_100)
// ---------------------------------------------------------------------------
__device__ __forceinline__ uint32_t smem_u32(const void* p) {
    uint32_t a;
    asm("{ .reg .u64 t; cvta.to.shared.u64 t, %1; cvt.u32.u64 %0, t; }" : "=r"(a) : "l"(p));
    return a;
}
__device__ __forceinline__ void cpa16(uint32_t dst, const void* src) {
    asm volatile("cp.async.cg.shared.global [%0], [%1], 16;" :: "r"(dst), "l"(src));
}
__device__ __forceinline__ void ldmx4(uint32_t* r, uint32_t addr) {
    asm volatile("ldmatrix.sync.aligned.m8n8.x4.shared.b16 {%0,%1,%2,%3}, [%4];"
                 : "=r"(r[0]), "=r"(r[1]), "=r"(r[2]), "=r"(r[3]) : "r"(addr));
}
__device__ __forceinline__ void mma16816(float* d, const uint32_t* a,
                                         uint32_t b0, uint32_t b1) {
    asm volatile(
        "mma.sync.aligned.m16n8k16.row.col.f32.bf16.bf16.f32 "
        "{%0,%1,%2,%3}, {%4,%5,%6,%7}, {%8,%9}, {%0,%1,%2,%3};"
        : "+f"(d[0]), "+f"(d[1]), "+f"(d[2]), "+f"(d[3])
        : "r"(a[0]), "r"(a[1]), "r"(a[2]), "r"(a[3]), "r"(b0), "r"(b1));
}
__device__ __forceinline__ void split2(float y, __nv_bfloat16& h, __nv_bfloat16& l) {
    h = __float2bfloat16_rn(y);
    l = __float2bfloat16_rn(y - __bfloat162float(h));
}

// ---------------------------------------------------------------------------
// Fused heterogeneous prep kernel (identical to R9/R10 — passed)
// ---------------------------------------------------------------------------
#define NN_BLKS   (BB * NPTS / 8)                         // 8192
#define F1_BLKS   ((NPTS / 32) * (C1V / 64) * BB)         // 8192
#define F2T_BLKS  ((MPTS / 32) * (C2V / 32) * BB)         // 4096
#define WS1_BLKS  (H1V * CIN / 256)                       // 512
#define WS2_BLKS  (H2V * H1V / 256)                       // 256
#define PREP_BLKS (NN_BLKS + F1_BLKS + F2T_BLKS + WS1_BLKS + WS2_BLKS)

__global__ __launch_bounds__(256) void prep_kernel(
    const float* __restrict__ xyz1, const float* __restrict__ xyz2,
    const float* __restrict__ feat1, const float* __restrict__ feat2,
    const float* __restrict__ w1, const float* __restrict__ w2)
{
    __shared__ __align__(16) char sbuf[16384];
    const int bid = blockIdx.x;
    const int tid = threadIdx.x;

    if (bid < NN_BLKS + F1_BLKS) {
        if ((bid & 1) == 0) {
            // ---------------- nn part ----------------
            float* sx = reinterpret_cast<float*>(sbuf);
            float* sy = sx + MPTS;
            float* sz = sy + MPTS;
            float* sn = sz + MPTS;
            const int warp = tid >> 5;
            const int lane = tid & 31;
            const int p0   = (bid >> 1) * 8;
            const int b    = p0 / NPTS;

            const float* x2 = xyz2 + (size_t)b * MPTS * 3;
            for (int i = tid; i < MPTS; i += 256) {
                float a = x2[i*3+0], c = x2[i*3+1], d = x2[i*3+2];
                sx[i] = a; sy[i] = c; sz[i] = d;
                sn[i] = a*a + c*c + d*d;
            }
            __syncthreads();

            const int n = (p0 + warp) % NPTS;
            const float* q = xyz1 + ((size_t)b * NPTS + n) * 3;
            const float qx = q[0], qy = q[1], qz = q[2];
            const float qn = qx*qx + qy*qy + qz*qz;

            float d0 = FLT_BIG, d1 = FLT_BIG, d2 = FLT_BIG;
            int   i0 = -1, i1 = -1, i2 = -1;

            #pragma unroll 4
            for (int j = 0; j < MPTS / 32; j++) {
                const int m = j * 32 + lane;
                const float dot = qx*sx[m] + qy*sy[m] + qz*sz[m];
                const float d = qn + sn[m] - 2.0f * dot;
                if (d < d2) {
                    if (d < d1) {
                        d2 = d1; i2 = i1;
                        if (d < d0) { d1 = d0; i1 = i0; d0 = d; i0 = m; }
                        else        { d1 = d;  i1 = m; }
                    } else { d2 = d; i2 = m; }
                }
            }

            float rd[3]; int ri[3];
            #pragma unroll
            for (int k = 0; k < 3; k++) {
                float v = d0;
                #pragma unroll
                for (int off = 16; off; off >>= 1)
                    v = fminf(v, __shfl_xor_sync(0xffffffffu, v, off));
                const unsigned mask = __ballot_sync(0xffffffffu, d0 == v);
                const int src = __ffs(mask) - 1;
                const int widx = __shfl_sync(0xffffffffu, i0, src);
                rd[k] = v; ri[k] = widx;
                if (lane == src) { d0 = d1; i0 = i1; d1 = d2; i1 = i2; d2 = FLT_BIG; i2 = -1; }
            }

            if (lane == 0) {
                const float w0 = 1.0f / (rd[0] + 1e-8f);
                const float w1v = 1.0f / (rd[1] + 1e-8f);
                const float w2v = 1.0f / (rd[2] + 1e-8f);
                const float s  = 1.0f / (w0 + w1v + w2v);
                const size_t base = ((size_t)b * NPTS + n) * 3;
                g_w[base+0] = w0 * s; g_w[base+1] = w1v * s; g_w[base+2] = w2v * s;
                g_idx[base+0] = ri[0]; g_idx[base+1] = ri[1]; g_idx[base+2] = ri[2];
            }
        } else {
            // ---------------- feat1 -> F1 split part ----------------
            float (*s)[65] = reinterpret_cast<float(*)[65]>(sbuf);
            const int f  = bid >> 1;
            const int n0 = (f & 127) * 32;
            const int c0 = ((f >> 7) & 3) * 64;
            const int b  = f >> 9;
            for (int i = tid; i < 64 * 32; i += 256) {
                const int cl = i >> 5, nl = i & 31;
                s[nl][cl] = feat1[((size_t)b * C1V + c0 + cl) * NPTS + n0 + nl];
            }
            __syncthreads();
            const int n_l = tid >> 3, seg = tid & 7;
            const size_t orow = ((size_t)(b * NPTS + n0 + n_l)) * C1V + c0 + seg * 8;
            __nv_bfloat16 h[8], l[8];
            #pragma unroll
            for (int t = 0; t < 8; t++) split2(s[n_l][seg * 8 + t], h[t], l[t]);
            *reinterpret_cast<uint4*>(g_F1h + orow) = *reinterpret_cast<uint4*>(h);
            *reinterpret_cast<uint4*>(g_F1l + orow) = *reinterpret_cast<uint4*>(l);
        }
    } else if (bid < NN_BLKS + F1_BLKS + F2T_BLKS) {
        // ---------------- feat2 transpose + split part ----------------
        float (*s)[33] = reinterpret_cast<float(*)[33]>(sbuf);
        const int t  = bid - (NN_BLKS + F1_BLKS);
        const int m0 = (t & 31) * 32;
        const int c0 = ((t >> 5) & 7) * 32;
        const int b  = t >> 8;
        for (int i = tid; i < 1024; i += 256) {
            const int cl = i >> 5, ml = i & 31;
            s[ml][cl] = feat2[((size_t)b * C2V + c0 + cl) * MPTS + m0 + ml];
        }
        __syncthreads();
        const int ml = tid >> 3, c4 = (tid & 7) * 4;
        __nv_bfloat16 h[4], l[4];
        #pragma unroll
        for (int q = 0; q < 4; q++) split2(s[ml][c4 + q], h[q], l[q]);
        const size_t dst = ((size_t)(b * MPTS + m0 + ml)) * C2V + c0 + c4;
        *reinterpret_cast<uint2*>(g_TF2h + dst) = *reinterpret_cast<uint2*>(h);
        *reinterpret_cast<uint2*>(g_TF2l + dst) = *reinterpret_cast<uint2*>(l);
    } else {
        // ---------------- weight split part ----------------
        const int u = bid - (NN_BLKS + F1_BLKS + F2T_BLKS);
        if (u < WS1_BLKS) {
            const int i = u * 256 + tid;            // over H1V*CIN
            const int o = i >> 9, c = i & 511;
            __nv_bfloat16 h, l;
            split2(w1[i], h, l);
            if (c < 256) { g_W1ah[o * 256 + c] = h; g_W1al[o * 256 + c] = l; }
            else         { g_W1bh[o * 256 + c - 256] = h; g_W1bl[o * 256 + c - 256] = l; }
        } else {
            const int i = (u - WS1_BLKS) * 256 + tid;
            split2(w2[i], g_W2h[i], g_W2l[i]);
        }
    }
}

// ---------------------------------------------------------------------------
// Gather kernel: G[b][n][:] = sum_j w_j * Y[b][m_j][:]. One warp per point,
// explicit float4 loads/stores (same structure as the proven 30us interp).
// ---------------------------------------------------------------------------
__global__ __launch_bounds__(256) void gather_kernel()
{
    const int warp = threadIdx.x >> 5;
    const int lane = threadIdx.x & 31;
    const int gn = blockIdx.x * 8 + warp;
    const int b = gn >> 12;
    const size_t p3 = (size_t)gn * 3;
    const int j0 = g_idx[p3], j1 = g_idx[p3+1], j2 = g_idx[p3+2];
    const float w0 = g_w[p3], w1v = g_w[p3+1], w2v = g_w[p3+2];
    const float* Y0 = g_Y + ((size_t)(b * MPTS + j0)) * H1V;
    const float* Y1 = g_Y + ((size_t)(b * MPTS + j1)) * H1V;
    const float* Y2 = g_Y + ((size_t)(b * MPTS + j2)) * H1V;
    float* G = g_G + (size_t)gn * H1V;

    #pragma unroll
    for (int half = 0; half < 2; half++) {
        const int c = half * 128 + lane * 4;
        const float4 a = *reinterpret_cast<const float4*>(Y0 + c);
        const float4 d = *reinterpret_cast<const float4*>(Y1 + c);
        const float4 e = *reinterpret_cast<const float4*>(Y2 + c);
        float4 o;
        o.x = w0*a.x + w1v*d.x + w2v*e.x;
        o.y = w0*a.y + w1v*d.y + w2v*e.y;
        o.z = w0*a.z + w1v*d.z + w2v*e.z;
        o.w = w0*a.w + w1v*d.w + w2v*e.w;
        *reinterpret_cast<float4*>(G + c) = o;
    }
}

// ---------------------------------------------------------------------------
// bf16-split GEMM via mma.sync + epilogue modes.
//   D[o-tile 128][n-tile 128] = sum_k A[o][k] * B[b][n][k]  (3 split terms)
// MODE 0: BN+ReLU, fp32 out [b][H2V][NPTS]           (layer 2)
// MODE 2: raw fp32 transposed out [b][NTOT][256]     (Y = W1a*feat2)
// MODE 3: + coalesced G add, BN+ReLU, bf16-split out [b][n][256] (layer 1)
// ---------------------------------------------------------------------------
#define SMEM_GEMM 65536

template<int KTOT, int NTOT, int MODE>
__global__ __launch_bounds__(256, 2)
void gemm_mma(const __nv_bfloat16* __restrict__ Ah, const __nv_bfloat16* __restrict__ Al,
              const __nv_bfloat16* __restrict__ Bh, const __nv_bfloat16* __restrict__ Bl,
              const float* __restrict__ gamma, const float* __restrict__ beta,
              float* __restrict__ outF, __nv_bfloat16* __restrict__ outH,
              __nv_bfloat16* __restrict__ outL,
              const float* __restrict__ Gg)
{
    extern __shared__ __align__(128) char smem[];
    const uint32_t sb = smem_u32(smem);
    const int tid  = threadIdx.x;
    const int wid  = tid >> 5;
    const int ln   = tid & 31;
    const int wrow = wid >> 2;
    const int wcol = wid & 3;
    const int n0   = blockIdx.x * 128;
    const int o0   = blockIdx.y * 128;
    const int b    = blockIdx.z;

    float acc[4][4][4];
    #pragma unroll
    for (int mi = 0; mi < 4; mi++)
        #pragma unroll
        for (int ni = 0; ni < 4; ni++)
            #pragma unroll
            for (int e = 0; e < 4; e++) acc[mi][ni][e] = 0.0f;

    constexpr int NC = KTOT / 32;

    const int rA  = wrow * 64 + (ln & 15);
    const int rB  = wcol * 32 + (ln & 15);
    const uint32_t sunit = (uint32_t)(ln >> 4);
    const uint32_t lswz  = (uint32_t)(ln & 7);

    auto load_chunk = [&](int c) {
        const uint32_t ab = sb + (uint32_t)(c & 1) * 32768u;
        const int k0 = c * 32;
        #pragma unroll
        for (int it = 0; it < 8; it++) {
            const int i = tid + it * 256;
            const int region = i >> 10;
            const int row = (i >> 3) & 127;
            const int s = i & 7;
            const uint32_t sw = (uint32_t)region * 16384u + (uint32_t)row * 128u
                              + (uint32_t)((s ^ (row & 7)) << 4);
            const int kofs = k0 + (s & 3) * 8;
            const void* src;
            if (region == 0)
                src = (s < 4 ? (const void*)(Ah + (size_t)(o0 + row) * KTOT + kofs)
                             : (const void*)(Al + (size_t)(o0 + row) * KTOT + kofs));
            else
                src = (s < 4 ? (const void*)(Bh + ((size_t)b * NTOT + n0 + row) * KTOT + kofs)
                             : (const void*)(Bl + ((size_t)b * NTOT + n0 + row) * KTOT + kofs));
            cpa16(ab + sw, src);
        }
        asm volatile("cp.async.commit_group;");
    };

    load_chunk(0);

    for (int c = 0; c < NC; c++) {
        if (c + 1 < NC) {
            load_chunk(c + 1);
            asm volatile("cp.async.wait_group 1;" ::: "memory");
        } else {
            asm volatile("cp.async.wait_group 0;" ::: "memory");
        }
        __syncthreads();

        const uint32_t ab = sb + (uint32_t)(c & 1) * 32768u;
        #pragma unroll
        for (int ks = 0; ks < 2; ks++) {
            const uint32_t scol = (uint32_t)(ks * 2) + sunit;
            const uint32_t kswzH = ((scol ^ lswz) << 4);
            const uint32_t kswzL = (((scol + 4u) ^ lswz) << 4);

            uint32_t bh[2][4], bl[2][4];
            #pragma unroll
            for (int np = 0; np < 2; np++) {
                const uint32_t rbase = 16384u + (uint32_t)(rB + np * 16) * 128u;
                ldmx4(bh[np], ab + rbase + kswzH);
                ldmx4(bl[np], ab + rbase + kswzL);
            }
            #pragma unroll
            for (int mi = 0; mi < 4; mi++) {
                const uint32_t abase = (uint32_t)(rA + mi * 16) * 128u;
                uint32_t ah[4], al[4];
                ldmx4(ah, ab + abase + kswzH);
                ldmx4(al, ab + abase + kswzL);
                #pragma unroll
                for (int ni = 0; ni < 4; ni++) {
                    const int np = ni >> 1, hf = ni & 1;
                    const uint32_t b0h = bh[np][hf], b1h = bh[np][2 + hf];
                    const uint32_t b0l = bl[np][hf], b1l = bl[np][2 + hf];
                    mma16816(acc[mi][ni], ah, b0h, b1h);
                    mma16816(acc[mi][ni], ah, b0l, b1l);
                    mma16816(acc[mi][ni], al, b0h, b1h);
                }
            }
        }
        __syncthreads();
    }

    // ---------------- epilogue ----------------
    const float inv = rsqrtf(1.0f + 1e-5f);
    const int g = ln >> 2, t = ln & 3;

    if (MODE == 0) {
        #pragma unroll
        for (int mi = 0; mi < 4; mi++) {
            const int o_a = o0 + wrow * 64 + mi * 16 + g;
            const int o_b = o_a + 8;
            const float scA = gamma[o_a] * inv, biA = beta[o_a];
            const float scB = gamma[o_b] * inv, biB = beta[o_b];
            float* rowA = outF + ((size_t)(b * H2V + o_a)) * NPTS + n0;
            float* rowB = outF + ((size_t)(b * H2V + o_b)) * NPTS + n0;
            #pragma unroll
            for (int ni = 0; ni < 4; ni++) {
                const int n = wcol * 32 + ni * 8 + 2 * t;
                float2 va, vb;
                va.x = fmaxf(fmaf(acc[mi][ni][0], scA, biA), 0.0f);
                va.y = fmaxf(fmaf(acc[mi][ni][1], scA, biA), 0.0f);
                vb.x = fmaxf(fmaf(acc[mi][ni][2], scB, biB), 0.0f);
                vb.y = fmaxf(fmaf(acc[mi][ni][3], scB, biB), 0.0f);
                *reinterpret_cast<float2*>(rowA + n) = va;
                *reinterpret_cast<float2*>(rowB + n) = vb;
            }
        }
    } else {
        // transpose through smem in two 64-o half-tiles; raw acc staged
        float* S = reinterpret_cast<float*>(smem);
        #pragma unroll
        for (int half = 0; half < 2; half++) {
            __syncthreads();
            if (wrow == half) {
                #pragma unroll
                for (int mi = 0; mi < 4; mi++) {
                    const int ol_a = mi * 16 + g;
                    const int ol_b = ol_a + 8;
                    #pragma unroll
                    for (int ni = 0; ni < 4; ni++) {
                        const int nl = wcol * 32 + ni * 8 + 2 * t;
                        S[ol_a * 129 + nl]     = acc[mi][ni][0];
                        S[ol_a * 129 + nl + 1] = acc[mi][ni][1];
                        S[ol_b * 129 + nl]     = acc[mi][ni][2];
                        S[ol_b * 129 + nl + 1] = acc[mi][ni][3];
                    }
                }
            }
            __syncthreads();
            const int n_l = tid >> 1, oh = (tid & 1) * 32;
            const int obase = o0 + half * 64 + oh;

            if (MODE == 2) {
                const size_t drow = ((size_t)(b * NTOT + n0 + n_l)) * H1V + obase;
                #pragma unroll
                for (int gs = 0; gs < 4; gs++) {
                    float v[8];
                    #pragma unroll
                    for (int t2 = 0; t2 < 8; t2++)
                        v[t2] = S[(oh + gs * 8 + t2) * 129 + n_l];
                    *reinterpret_cast<float4*>(outF + drow + gs * 8)     = *reinterpret_cast<float4*>(v);
                    *reinterpret_cast<float4*>(outF + drow + gs * 8 + 4) = *reinterpret_cast<float4*>(v + 4);
                }
            } else { // MODE == 3: coalesced G add + BN + ReLU + split
                const size_t drow = ((size_t)(b * NPTS + n0 + n_l)) * H1V + obase;
                #pragma unroll
                for (int gs = 0; gs < 4; gs++) {
                    const float4 g0 = *reinterpret_cast<const float4*>(Gg + drow + gs * 8);
                    const float4 g1 = *reinterpret_cast<const float4*>(Gg + drow + gs * 8 + 4);
                    const float gv[8] = {g0.x, g0.y, g0.z, g0.w, g1.x, g1.y, g1.z, g1.w};
                    __nv_bfloat16 h[8], l[8];
                    #pragma unroll
                    for (int t2 = 0; t2 < 8; t2++) {
                        const int og = obase + gs * 8 + t2;
                        const float z = S[(oh + gs * 8 + t2) * 129 + n_l] + gv[t2];
                        const float y = fmaxf(fmaf(z, gamma[og] * inv, beta[og]), 0.0f);
                        split2(y, h[t2], l[t2]);
                    }
                    *reinterpret_cast<uint4*>(outH + drow + gs * 8) = *reinterpret_cast<uint4*>(h);
                    *reinterpret_cast<uint4*>(outL + drow + gs * 8) = *reinterpret_cast<uint4*>(l);
                }
            }
        }
    }
}

// ---------------------------------------------------------------------------
extern "C" void kernel_launch(void* const* d_in, const int* in_sizes, int n_in,
                              void* d_out, int out_size)
{
    const float* xyz1   = (const float*)d_in[0];
    const float* xyz2   = (const float*)d_in[1];
    const float* feat1  = (const float*)d_in[2];
    const float* feat2  = (const float*)d_in[3];
    const float* w1     = (const float*)d_in[4];
    const float* gamma1 = (const float*)d_in[5];
    const float* beta1  = (const float*)d_in[6];
    const float* w2     = (const float*)d_in[7];
    const float* gamma2 = (const float*)d_in[8];
    const float* beta2  = (const float*)d_in[9];
    float* out = (float*)d_out;

    __nv_bfloat16 *F1h, *F1l, *TF2h, *TF2l, *X1h, *X1l;
    __nv_bfloat16 *W1ah, *W1al, *W1bh, *W1bl, *W2h, *W2l;
    float *Yg, *Gg;
    cudaGetSymbolAddress((void**)&F1h,  g_F1h);
    cudaGetSymbolAddress((void**)&F1l,  g_F1l);
    cudaGetSymbolAddress((void**)&TF2h, g_TF2h);
    cudaGetSymbolAddress((void**)&TF2l, g_TF2l);
    cudaGetSymbolAddress((void**)&X1h,  g_X1h);
    cudaGetSymbolAddress((void**)&X1l,  g_X1l);
    cudaGetSymbolAddress((void**)&W1ah, g_W1ah);
    cudaGetSymbolAddress((void**)&W1al, g_W1al);
    cudaGetSymbolAddress((void**)&W1bh, g_W1bh);
    cudaGetSymbolAddress((void**)&W1bl, g_W1bl);
    cudaGetSymbolAddress((void**)&W2h,  g_W2h);
    cudaGetSymbolAddress((void**)&W2l,  g_W2l);
    cudaGetSymbolAddress((void**)&Yg,   g_Y);
    cudaGetSymbolAddress((void**)&Gg,   g_G);

    cudaFuncSetAttribute(gemm_mma<C2V, MPTS, 2>, cudaFuncAttributeMaxDynamicSharedMemorySize, SMEM_GEMM);
    cudaFuncSetAttribute(gemm_mma<C1V, NPTS, 3>, cudaFuncAttributeMaxDynamicSharedMemorySize, SMEM_GEMM);
    cudaFuncSetAttribute(gemm_mma<H1V, NPTS, 0>, cudaFuncAttributeMaxDynamicSharedMemorySize, SMEM_GEMM);

    // 1) fused heterogeneous prep
    prep_kernel<<<PREP_BLKS, 256>>>(xyz1, xyz2, feat1, feat2, w1, w2);

    // 2) Y = W1a * feat2  -> [b][m][o] fp32 (raw, no BN)
    gemm_mma<C2V, MPTS, 2><<<dim3(MPTS / 128, H1V / 128, BB), 256, SMEM_GEMM>>>(
        W1ah, W1al, TF2h, TF2l, nullptr, nullptr, Yg, nullptr, nullptr, nullptr);

    // 3) G = gather(Y; idx, w)  (streaming, float4)
    gather_kernel<<<BB * NPTS / 8, 256>>>();

    // 4) layer 1 = W1b*feat1 + G, BN+ReLU, split -> X1
    gemm_mma<C1V, NPTS, 3><<<dim3(NPTS / 128, H1V / 128, BB), 256, SMEM_GEMM>>>(
        W1bh, W1bl, F1h, F1l, gamma1, beta1, nullptr, X1h, X1l, Gg);

    // 5) layer 2: W2 * X1 -> out fp32 [b][256][n], BN+ReLU
    gemm_mma<H1V, NPTS, 0><<<dim3(NPTS / 128, H2V / 128, BB), 256, SMEM_GEMM>>>(
        W2h, W2l, X1h, X1l, gamma2, beta2, out, nullptr, nullptr, nullptr);
}